// round 14
// baseline (speedup 1.0000x reference)
#include <cuda_runtime.h>
#include <cuda_bf16.h>
#include <cstdint>

#define BB 4
#define LL 128
#define DD 256
#define TWO_D 512

// Gram scratch: [b][type][r][k], types: 0=0.5*Q.V^T(+mask), 1=0.5*V.V^T,
//                                        2=0.5*Q.Q^T(+mask), 3=0.5*V.Q^T
__device__ float g_gram[BB * 4 * LL * LL];

// Pre-split bf16 planes of V and Q: [b][tensor(0=V,1=Q)][plane(0=hi,1=lo)][k][d]
__device__ __nv_bfloat16 g_bf[BB * 2 * 2 * LL * DD];

// Mask compaction lists: pair = b*128 + i
__device__ int g_active[BB * LL];
__device__ int g_inactive[BB * LL];
__device__ int g_nactive;

// ---------------------------------------------------------------------------
// Kernel 1: Gram matrices. grid (32, B). 256 threads. 16 rows per block.
// Every block also converts its share of V/Q into bf16 hi/lo planes.
// Block (0,0) additionally compacts the mask.
// ---------------------------------------------------------------------------
__global__ __launch_bounds__(256) void gram_kernel(
    const float* __restrict__ Q, const float* __restrict__ V,
    const int* __restrict__ mask)
{
    int t = threadIdx.x;

    if (blockIdx.x == 0 && blockIdx.y == 0) {
        __shared__ int cA, cI;
        if (t == 0) { cA = 0; cI = 0; }
        __syncthreads();
        for (int e = t; e < BB * LL; e += 256) {
            if (mask[e]) g_active[atomicAdd(&cA, 1)] = e;
            else         g_inactive[atomicAdd(&cI, 1)] = e;
        }
        __syncthreads();
        if (t == 0) g_nactive = cA;
    }

    // ---- bf16 plane conversion: 128 blocks x 2048 elements ----
    {
        int blk = blockIdx.y * 32 + blockIdx.x;      // 0..127
        #pragma unroll
        for (int u = 0; u < 8; u++) {
            int e = blk * 2048 + t + u * 256;        // 0..262143
            int tb    = e >> 15;                     // 0..7 = b*2 + tensor
            int inner = e & 32767;                   // k*256 + d
            int bb = tb >> 1, tensor = tb & 1;
            const float* src = (tensor ? Q : V) + (size_t)bb * LL * DD;
            float x = src[inner];
            __nv_bfloat16 h = __float2bfloat16(x);
            __nv_bfloat16 l = __float2bfloat16(x - __bfloat162float(h));
            size_t base = (size_t)(tb * 2) * (LL * DD);
            g_bf[base + inner]           = h;
            g_bf[base + LL * DD + inner] = l;
        }
    }

    int b    = blockIdx.y;
    int type = blockIdx.x >> 3;       // 0..3
    int rq   = blockIdx.x & 7;        // 0..7
    const float* A  = ((type & 1) ? V : Q) + (size_t)b * LL * DD;
    const float* Bm = ((type < 2) ? V : Q) + (size_t)b * LL * DD;
    int r0 = rq * 16;

    __shared__ float sA[16 * 65];
    __shared__ float sB[128 * 65];

    float acc[2][4] = {};

    for (int dc = 0; dc < DD; dc += 64) {
        #pragma unroll
        for (int u = 0; u < 32; u++) {
            int idx = t + u * 256;               // 0..8191
            int r = idx >> 6, d = idx & 63;
            sB[r * 65 + d] = Bm[r * DD + dc + d];
        }
        #pragma unroll
        for (int u = 0; u < 4; u++) {
            int idx = t + u * 256;               // 0..1023
            int r = idx >> 6, d = idx & 63;
            sA[r * 65 + d] = A[(r0 + r) * DD + dc + d];
        }
        __syncthreads();

        int rg = t >> 5, kg = t & 31;
        const float* sAr = sA + rg * 2 * 65;
        const float* sBr = sB + kg * 4 * 65;
        #pragma unroll 8
        for (int d = 0; d < 64; d++) {
            float av[2], bv[4];
            #pragma unroll
            for (int a = 0; a < 2; a++) av[a] = sAr[a * 65 + d];
            #pragma unroll
            for (int c = 0; c < 4; c++) bv[c] = sBr[c * 65 + d];
            #pragma unroll
            for (int a = 0; a < 2; a++)
                #pragma unroll
                for (int c = 0; c < 4; c++)
                    acc[a][c] = fmaf(av[a], bv[c], acc[a][c]);
        }
        __syncthreads();
    }

    int rg = t >> 5, kg = t & 31;
    float* G = g_gram + (size_t)(b * 4 + type) * LL * LL;
    bool doMask = (type == 0) || (type == 2);
    #pragma unroll
    for (int a = 0; a < 2; a++) {
        #pragma unroll
        for (int c = 0; c < 4; c++) {
            int k = kg * 4 + c;
            float val = 0.5f * acc[a][c];
            if (doMask && mask[b * LL + k] == 0) val = -1e30f;
            G[(r0 + rg * 2 + a) * LL + k] = val;
        }
    }
}

// ---------------------------------------------------------------------------
// mma.sync / ldmatrix / cp.async helpers
// ---------------------------------------------------------------------------
__device__ __forceinline__ void mma_bf16(float* c, const uint32_t* a,
                                         uint32_t b0, uint32_t b1)
{
    asm volatile(
        "mma.sync.aligned.m16n8k16.row.col.f32.bf16.bf16.f32 "
        "{%0,%1,%2,%3}, {%4,%5,%6,%7}, {%8,%9}, {%0,%1,%2,%3};"
        : "+f"(c[0]), "+f"(c[1]), "+f"(c[2]), "+f"(c[3])
        : "r"(a[0]), "r"(a[1]), "r"(a[2]), "r"(a[3]), "r"(b0), "r"(b1));
}
__device__ __forceinline__ void ldsm_x4(uint32_t* r, uint32_t addr)
{
    asm volatile("ldmatrix.sync.aligned.m8n8.x4.shared.b16 {%0,%1,%2,%3}, [%4];"
        : "=r"(r[0]), "=r"(r[1]), "=r"(r[2]), "=r"(r[3]) : "r"(addr));
}
__device__ __forceinline__ void ldsm_x4_t(uint32_t* r, uint32_t addr)
{
    asm volatile("ldmatrix.sync.aligned.m8n8.x4.trans.shared.b16 {%0,%1,%2,%3}, [%4];"
        : "=r"(r[0]), "=r"(r[1]), "=r"(r[2]), "=r"(r[3]) : "r"(addr));
}
__device__ __forceinline__ void cp16(uint32_t dst, const void* src)
{
    asm volatile("cp.async.cg.shared.global [%0], [%1], 16;"
                 :: "r"(dst), "l"(src) : "memory");
}
#define CP_COMMIT() asm volatile("cp.async.commit_group;" ::: "memory")
#define CP_WAIT0()  asm volatile("cp.async.wait_group 0;" ::: "memory")

// ---------------------------------------------------------------------------
// Kernel 2: attention via mma.sync bf16x3 + LayerNorm.
// TWO blocks per (b,i) (j-halves of 64 rows), 256 threads, 3 CTAs/SM.
// V/Q tiles arrive pre-split as bf16 planes via cp.async (no conversion,
// no register staging). Warp tile 32j x 16d; macro = 64j x 64d.
// P planes [64 j][136 k] bf16 (hi/lo); V quarter [128 k][72 d] bf16 K-major.
// ---------------------------------------------------------------------------
#define NT 256
#define PSTR 136
#define VSTR 72
// byte offsets in dynamic smem
#define OB_PHI   0                     // 64*136*2 = 17408
#define OB_PLO   17408                 // 17408
#define OB_V     34816                 // 2 x 18432 (hi, lo)
#define VPL      18432                 // bytes per V plane
#define OB_G1    71680                 // 128 f
#define OB_G1Q   72192                 // 128 f
#define OB_W     72704                 // 512 f
#define OB_BI    74752                 // 512 f
// stats overlay the V region (dead by epilogue)
#define OB_ST1   OB_V                  // 64*4 f
#define OB_ST2   (OB_V + 1024)         // 64*4 f
#define OB_MU    (OB_V + 2048)         // 64 f
#define OB_RS    (OB_V + 2304)         // 64 f
#define SMEM_BYTES 76800

__global__ __launch_bounds__(NT, 3) void attn_kernel(
    const float* __restrict__ Q, const float* __restrict__ V,
    const float* __restrict__ nw, const float* __restrict__ nb,
    float* __restrict__ out)
{
    int bid = blockIdx.x;
    int t   = threadIdx.x;
    int nA  = g_nactive;
    int pairIdx = bid >> 1;
    int jh      = bid & 1;            // j half: rows jh*64 .. jh*64+63
    bool active = (pairIdx < nA);
    int pair = active ? g_active[pairIdx] : g_inactive[pairIdx - nA];
    int b = pair >> 7, i = pair & 127;
    float* outBase = out + (((size_t)(b * LL + i)) * LL + jh * 64) * TWO_D;

    if (!active) {
        float4 z = make_float4(0.f, 0.f, 0.f, 0.f);
        float4* o4 = (float4*)outBase;
        #pragma unroll
        for (int u = 0; u < 32; u++) o4[t + u * NT] = z;
        return;
    }

    extern __shared__ char smc[];
    uint32_t smb = (uint32_t)__cvta_generic_to_shared(smc);

    __nv_bfloat16* sPhi = (__nv_bfloat16*)(smc + OB_PHI);
    __nv_bfloat16* sPlo = (__nv_bfloat16*)(smc + OB_PLO);
    float* sG1  = (float*)(smc + OB_G1);
    float* sG1q = (float*)(smc + OB_G1Q);
    float* sW   = (float*)(smc + OB_W);
    float* sBi  = (float*)(smc + OB_BI);
    float* sST1 = (float*)(smc + OB_ST1);
    float* sST2 = (float*)(smc + OB_ST2);
    float* sMu  = (float*)(smc + OB_MU);
    float* sRs  = (float*)(smc + OB_RS);

    const float* G   = g_gram + (size_t)b * 4 * LL * LL;
    const float* G2  = G + 1 * LL * LL;   // 0.5*V.V^T
    const float* G2q = G + 3 * LL * LL;   // 0.5*V.Q^T

    int warp = t >> 5, lane = t & 31;
    int g  = lane >> 2;      // 0..7
    int tq = lane & 3;       // 0..3
    int jg     = warp >> 2;         // 0..1 -> 32 local j rows
    int dgroup = warp & 3;          // 0..3 -> 16 d cols within 64-d quarter
    int mbase = jg * 32;            // local row base

    // ldmatrix lane addressing (mat = lane>>3, mr = lane&7)
    int mat = lane >> 3, mr = lane & 7;
    uint32_t aAddrH = smb + OB_PHI +
        (uint32_t)(((mbase + (mat & 1) * 8 + mr) * PSTR + (mat >> 1) * 8) * 2);
    uint32_t aAddrL = aAddrH + (OB_PLO - OB_PHI);
    uint32_t bBase = smb + OB_V +
        (uint32_t)((((mat & 1) * 8 + mr) * VSTR + dgroup * 16 + (mat >> 1) * 8) * 2);

    if (t < 128) {
        sG1[t]  = G[i * LL + t];                 // masked 0.5*q_i . v_k
        sG1q[t] = G[2 * LL * LL + i * LL + t];   // masked 0.5*q_i . q_k
    }
    #pragma unroll
    for (int u = 0; u < 2; u++) {
        sW[t + u * NT]  = nw[t + u * NT];
        sBi[t + u * NT] = nb[t + u * NT];
    }

    // cp.async tile load: [128 k][64 d] bf16 x 2 planes from g_bf.
    // 1024 16B-chunks per plane; thread does 4 chunks per plane.
    auto load_v_async = [&](int tensor, int dbase) {
        const __nv_bfloat16* baseH =
            g_bf + (size_t)((b * 2 + tensor) * 2) * (LL * DD);
        const __nv_bfloat16* baseL = baseH + LL * DD;
        #pragma unroll
        for (int u = 0; u < 4; u++) {
            int idx = t + u * NT;            // 0..1023
            int k = idx >> 3, c = idx & 7;   // row, 16B chunk
            uint32_t dofs = (uint32_t)(k * (VSTR * 2) + c * 16);
            cp16(smb + OB_V + dofs,       baseH + k * DD + dbase + c * 8);
            cp16(smb + OB_V + VPL + dofs, baseL + k * DD + dbase + c * 8);
        }
        CP_COMMIT();
    };

    // softmax over this CTA's 64 j rows (global row = jh*64 + jj)
    auto softmax_side = [&](const float* Grow, const float* g1) {
        for (int jj = warp; jj < 64; jj += 8) {
            const float* r = Grow + (jh * 64 + jj) * LL;
            float s0 = g1[lane]      + r[lane];
            float s1 = g1[lane + 32] + r[lane + 32];
            float s2 = g1[lane + 64] + r[lane + 64];
            float s3 = g1[lane + 96] + r[lane + 96];
            float m = fmaxf(fmaxf(s0, s1), fmaxf(s2, s3));
            #pragma unroll
            for (int o = 16; o; o >>= 1) m = fmaxf(m, __shfl_xor_sync(0xffffffffu, m, o));
            float e0 = __expf(s0 - m), e1 = __expf(s1 - m);
            float e2 = __expf(s2 - m), e3 = __expf(s3 - m);
            float su = e0 + e1 + e2 + e3;
            #pragma unroll
            for (int o = 16; o; o >>= 1) su += __shfl_xor_sync(0xffffffffu, su, o);
            float inv = 1.0f / su;
            float vals[4] = {e0 * inv, e1 * inv, e2 * inv, e3 * inv};
            #pragma unroll
            for (int c = 0; c < 4; c++) {
                int k = lane + c * 32;
                float x = vals[c];
                __nv_bfloat16 h = __float2bfloat16(x);
                __nv_bfloat16 l = __float2bfloat16(x - __bfloat162float(h));
                sPhi[jj * PSTR + k] = h;
                sPlo[jj * PSTR + k] = l;
            }
        }
    };

    // ---- prologue: async-load tile0 (V, quarter 0), softmax side 0 ----
    load_v_async(0, 0);
    __syncthreads();                 // sG1/sG1q/sW/sBi visible
    softmax_side(G2, sG1);
    CP_WAIT0();
    __syncthreads();

    float ls1[4] = {}, ls2[4] = {};

    // ---- 8 macro-iterations: (side, d-quarter) over 64j x 64d each ----
    #pragma unroll 1
    for (int mi = 0; mi < 8; mi++) {
        int s  = mi >> 2;
        int dq = mi & 3;

        // ---- MMA: warp tile 32j x 16d, k = 128 ----
        float acc[2][2][4] = {};
        #pragma unroll
        for (int kt = 0; kt < 8; kt++) {
            uint32_t ah0[4], ah1[4], al0[4], al1[4], bh[4], bl[4];
            uint32_t ka = (uint32_t)(kt * 32);
            uint32_t kb = (uint32_t)(kt * 16 * VSTR * 2);
            ldsm_x4(ah0, aAddrH + ka);
            ldsm_x4(ah1, aAddrH + 16 * PSTR * 2 + ka);
            ldsm_x4(al0, aAddrL + ka);
            ldsm_x4(al1, aAddrL + 16 * PSTR * 2 + ka);
            ldsm_x4_t(bh, bBase + kb);
            ldsm_x4_t(bl, bBase + VPL + kb);
            // hi*hi
            mma_bf16(acc[0][0], ah0, bh[0], bh[1]);
            mma_bf16(acc[0][1], ah0, bh[2], bh[3]);
            mma_bf16(acc[1][0], ah1, bh[0], bh[1]);
            mma_bf16(acc[1][1], ah1, bh[2], bh[3]);
            // hi*lo
            mma_bf16(acc[0][0], ah0, bl[0], bl[1]);
            mma_bf16(acc[0][1], ah0, bl[2], bl[3]);
            mma_bf16(acc[1][0], ah1, bl[0], bl[1]);
            mma_bf16(acc[1][1], ah1, bl[2], bl[3]);
            // lo*hi
            mma_bf16(acc[0][0], al0, bh[0], bh[1]);
            mma_bf16(acc[0][1], al0, bh[2], bh[3]);
            mma_bf16(acc[1][0], al1, bh[0], bh[1]);
            mma_bf16(acc[1][1], al1, bh[2], bh[3]);
        }

        // ---- store raw output + accumulate LN stats ----
        int colb = s * 256 + dq * 64 + dgroup * 16;
        #pragma unroll
        for (int mt = 0; mt < 2; mt++)
            #pragma unroll
            for (int nt = 0; nt < 2; nt++) {
                const float* a4 = acc[mt][nt];
                int r0 = mbase + mt * 16 + g;           // local row
                int c0 = colb + nt * 8 + tq * 2;
                *(float2*)&outBase[(size_t)r0 * TWO_D + c0] =
                    make_float2(a4[0], a4[1]);
                *(float2*)&outBase[(size_t)(r0 + 8) * TWO_D + c0] =
                    make_float2(a4[2], a4[3]);
                ls1[mt * 2 + 0] += a4[0] + a4[1];
                ls2[mt * 2 + 0] = fmaf(a4[0], a4[0], fmaf(a4[1], a4[1], ls2[mt * 2 + 0]));
                ls1[mt * 2 + 1] += a4[2] + a4[3];
                ls2[mt * 2 + 1] = fmaf(a4[2], a4[2], fmaf(a4[3], a4[3], ls2[mt * 2 + 1]));
            }
        __syncthreads();          // V buffer + P free to overwrite

        if (mi < 7) {
            int nx = mi + 1;
            load_v_async(nx >> 2, (nx & 3) * 64);   // async in flight...
            if (mi == 3) softmax_side(G2q, sG1q);   // ...overlapped with softmax
            CP_WAIT0();
            __syncthreads();
        }
    }

    // ---- LN stats: shfl-reduce across quad lanes, then smem reduce ----
    #pragma unroll
    for (int ss = 0; ss < 4; ss++) {
        float v1 = ls1[ss], v2 = ls2[ss];
        v1 += __shfl_xor_sync(0xffffffffu, v1, 1);
        v1 += __shfl_xor_sync(0xffffffffu, v1, 2);
        v2 += __shfl_xor_sync(0xffffffffu, v2, 1);
        v2 += __shfl_xor_sync(0xffffffffu, v2, 2);
        if (tq == 0) {
            int row = mbase + (ss >> 1) * 16 + (ss & 1) * 8 + g;   // local
            sST1[row * 4 + dgroup] = v1;
            sST2[row * 4 + dgroup] = v2;
        }
    }
    __syncthreads();
    if (t < 64) {
        float a1 = sST1[t * 4 + 0] + sST1[t * 4 + 1] + sST1[t * 4 + 2] + sST1[t * 4 + 3];
        float a2 = sST2[t * 4 + 0] + sST2[t * 4 + 1] + sST2[t * 4 + 2] + sST2[t * 4 + 3];
        float mu  = a1 * (1.0f / 512.0f);
        float var = a2 * (1.0f / 512.0f) - mu * mu;
        sMu[t] = mu;
        sRs[t] = rsqrtf(var + 1e-5f);
    }
    __syncthreads();

    // ---- Phase C: LayerNorm in place (region is L2-hot) ----
    int jr = t >> 2, part = t & 3;                  // local row, 4 thr/row
    float mu = sMu[jr], rs = sRs[jr];
    float* orow = outBase + (size_t)jr * TWO_D;
    #pragma unroll 4
    for (int itc = 0; itc < 32; itc++) {
        int idx4 = itc * 4 + part;       // 0..127
        int d = idx4 * 4;
        float4 x = *(float4*)&orow[d];
        x.x = (x.x - mu) * rs * sW[d + 0] + sBi[d + 0];
        x.y = (x.y - mu) * rs * sW[d + 1] + sBi[d + 1];
        x.z = (x.z - mu) * rs * sW[d + 2] + sBi[d + 2];
        x.w = (x.w - mu) * rs * sW[d + 3] + sBi[d + 3];
        *(float4*)&orow[d] = x;
    }
}

// ---------------------------------------------------------------------------
extern "C" void kernel_launch(void* const* d_in, const int* in_sizes, int n_in,
                              void* d_out, int out_size)
{
    const float* q    = (const float*)d_in[0];
    const float* v    = (const float*)d_in[1];
    const int*   mask = (const int*)d_in[2];
    const float* nw   = (const float*)d_in[3];
    const float* nb   = (const float*)d_in[4];
    float* out = (float*)d_out;

    gram_kernel<<<dim3(32, BB), 256>>>(q, v, mask);

    cudaFuncSetAttribute(attn_kernel,
                         cudaFuncAttributeMaxDynamicSharedMemorySize, SMEM_BYTES);
    attn_kernel<<<2 * BB * LL, NT, SMEM_BYTES>>>(q, v, nw, nb, out);
}

// round 15
// speedup vs baseline: 1.0984x; 1.0984x over previous
#include <cuda_runtime.h>
#include <cuda_bf16.h>
#include <cstdint>

#define BB 4
#define LL 128
#define DD 256
#define TWO_D 512

// Gram scratch: [b][type][r][k], types: 0=0.5*Q.V^T(+mask), 1=0.5*V.V^T,
//                                        2=0.5*Q.Q^T(+mask), 3=0.5*V.Q^T
__device__ float g_gram[BB * 4 * LL * LL];

// Pre-split bf16 planes of V and Q: [b][tensor(0=V,1=Q)][plane(0=hi,1=lo)][k][d]
__device__ __nv_bfloat16 g_bf[BB * 2 * 2 * LL * DD];

// Mask compaction lists: pair = b*128 + i
__device__ int g_active[BB * LL];
__device__ int g_inactive[BB * LL];
__device__ int g_nactive;

// ---------------------------------------------------------------------------
// Kernel 1: Gram matrices. grid (32, B). 256 threads. 16 rows per block.
// Every block also converts its share of V/Q into bf16 hi/lo planes.
// Block (0,0) additionally compacts the mask.
// ---------------------------------------------------------------------------
__global__ __launch_bounds__(256) void gram_kernel(
    const float* __restrict__ Q, const float* __restrict__ V,
    const int* __restrict__ mask)
{
    int t = threadIdx.x;

    if (blockIdx.x == 0 && blockIdx.y == 0) {
        __shared__ int cA, cI;
        if (t == 0) { cA = 0; cI = 0; }
        __syncthreads();
        for (int e = t; e < BB * LL; e += 256) {
            if (mask[e]) g_active[atomicAdd(&cA, 1)] = e;
            else         g_inactive[atomicAdd(&cI, 1)] = e;
        }
        __syncthreads();
        if (t == 0) g_nactive = cA;
    }

    // ---- bf16 plane conversion: 128 blocks x 2048 elements ----
    {
        int blk = blockIdx.y * 32 + blockIdx.x;      // 0..127
        #pragma unroll
        for (int u = 0; u < 8; u++) {
            int e = blk * 2048 + t + u * 256;        // 0..262143
            int tb    = e >> 15;                     // 0..7 = b*2 + tensor
            int inner = e & 32767;                   // k*256 + d
            int bb = tb >> 1, tensor = tb & 1;
            const float* src = (tensor ? Q : V) + (size_t)bb * LL * DD;
            float x = src[inner];
            __nv_bfloat16 h = __float2bfloat16(x);
            __nv_bfloat16 l = __float2bfloat16(x - __bfloat162float(h));
            size_t base = (size_t)(tb * 2) * (LL * DD);
            g_bf[base + inner]           = h;
            g_bf[base + LL * DD + inner] = l;
        }
    }

    int b    = blockIdx.y;
    int type = blockIdx.x >> 3;       // 0..3
    int rq   = blockIdx.x & 7;        // 0..7
    const float* A  = ((type & 1) ? V : Q) + (size_t)b * LL * DD;
    const float* Bm = ((type < 2) ? V : Q) + (size_t)b * LL * DD;
    int r0 = rq * 16;

    __shared__ float sA[16 * 65];
    __shared__ float sB[128 * 65];

    float acc[2][4] = {};

    for (int dc = 0; dc < DD; dc += 64) {
        #pragma unroll
        for (int u = 0; u < 32; u++) {
            int idx = t + u * 256;               // 0..8191
            int r = idx >> 6, d = idx & 63;
            sB[r * 65 + d] = Bm[r * DD + dc + d];
        }
        #pragma unroll
        for (int u = 0; u < 4; u++) {
            int idx = t + u * 256;               // 0..1023
            int r = idx >> 6, d = idx & 63;
            sA[r * 65 + d] = A[(r0 + r) * DD + dc + d];
        }
        __syncthreads();

        int rg = t >> 5, kg = t & 31;
        const float* sAr = sA + rg * 2 * 65;
        const float* sBr = sB + kg * 4 * 65;
        #pragma unroll 8
        for (int d = 0; d < 64; d++) {
            float av[2], bv[4];
            #pragma unroll
            for (int a = 0; a < 2; a++) av[a] = sAr[a * 65 + d];
            #pragma unroll
            for (int c = 0; c < 4; c++) bv[c] = sBr[c * 65 + d];
            #pragma unroll
            for (int a = 0; a < 2; a++)
                #pragma unroll
                for (int c = 0; c < 4; c++)
                    acc[a][c] = fmaf(av[a], bv[c], acc[a][c]);
        }
        __syncthreads();
    }

    int rg = t >> 5, kg = t & 31;
    float* G = g_gram + (size_t)(b * 4 + type) * LL * LL;
    bool doMask = (type == 0) || (type == 2);
    #pragma unroll
    for (int a = 0; a < 2; a++) {
        #pragma unroll
        for (int c = 0; c < 4; c++) {
            int k = kg * 4 + c;
            float val = 0.5f * acc[a][c];
            if (doMask && mask[b * LL + k] == 0) val = -1e30f;
            G[(r0 + rg * 2 + a) * LL + k] = val;
        }
    }
}

// ---------------------------------------------------------------------------
// mma.sync / ldmatrix / cp.async helpers
// ---------------------------------------------------------------------------
__device__ __forceinline__ void mma_bf16(float* c, const uint32_t* a,
                                         uint32_t b0, uint32_t b1)
{
    asm volatile(
        "mma.sync.aligned.m16n8k16.row.col.f32.bf16.bf16.f32 "
        "{%0,%1,%2,%3}, {%4,%5,%6,%7}, {%8,%9}, {%0,%1,%2,%3};"
        : "+f"(c[0]), "+f"(c[1]), "+f"(c[2]), "+f"(c[3])
        : "r"(a[0]), "r"(a[1]), "r"(a[2]), "r"(a[3]), "r"(b0), "r"(b1));
}
__device__ __forceinline__ void ldsm_x4(uint32_t* r, uint32_t addr)
{
    asm volatile("ldmatrix.sync.aligned.m8n8.x4.shared.b16 {%0,%1,%2,%3}, [%4];"
        : "=r"(r[0]), "=r"(r[1]), "=r"(r[2]), "=r"(r[3]) : "r"(addr));
}
__device__ __forceinline__ void ldsm_x4_t(uint32_t* r, uint32_t addr)
{
    asm volatile("ldmatrix.sync.aligned.m8n8.x4.trans.shared.b16 {%0,%1,%2,%3}, [%4];"
        : "=r"(r[0]), "=r"(r[1]), "=r"(r[2]), "=r"(r[3]) : "r"(addr));
}
__device__ __forceinline__ void cp16(uint32_t dst, const void* src)
{
    asm volatile("cp.async.cg.shared.global [%0], [%1], 16;"
                 :: "r"(dst), "l"(src) : "memory");
}
#define CP_COMMIT() asm volatile("cp.async.commit_group;" ::: "memory")
#define CP_WAIT0()  asm volatile("cp.async.wait_group 0;" ::: "memory")

// ---------------------------------------------------------------------------
// Kernel 2: attention via mma.sync bf16x3 + LayerNorm.
// TWO blocks per (b,i) (j-halves of 64 rows), 256 threads, 2 CTAs/SM.
// DOUBLE-BUFFERED V tiles: cp.async for tile n+1 issues BEFORE tile n's MMA,
// wait lands AFTER it — gmem latency fully hidden. Side-1 softmax overlaps
// its next tile's flight. Warp tile 32j x 16d; macro = 64j x 64d.
// P planes [64 j][136 k] bf16 (hi/lo); V tile [128 k][72 d] bf16 K-major.
// ---------------------------------------------------------------------------
#define NT 256
#define PSTR 136
#define VSTR 72
// byte offsets in dynamic smem
#define OB_PHI   0                     // 64*136*2 = 17408
#define OB_PLO   17408                 // 17408
#define OB_V     34816                 // 2 bufs x (2 planes x 18432) = 73728
#define VPL      18432                 // bytes per V plane
#define VBUF     36864                 // bytes per V buffer (hi+lo)
#define OB_G1    108544                // 128 f
#define OB_G1Q   109056                // 128 f
#define OB_W     109568                // 512 f
#define OB_BI    111616                // 512 f
// stats overlay the V region (dead by epilogue)
#define OB_ST1   OB_V                  // 64*4 f
#define OB_ST2   (OB_V + 1024)         // 64*4 f
#define OB_MU    (OB_V + 2048)         // 64 f
#define OB_RS    (OB_V + 2304)         // 64 f
#define SMEM_BYTES 113664              // x2 CTAs = 227328 <= 233472

__global__ __launch_bounds__(NT, 2) void attn_kernel(
    const float* __restrict__ Q, const float* __restrict__ V,
    const float* __restrict__ nw, const float* __restrict__ nb,
    float* __restrict__ out)
{
    int bid = blockIdx.x;
    int t   = threadIdx.x;
    int nA  = g_nactive;
    int pairIdx = bid >> 1;
    int jh      = bid & 1;            // j half: rows jh*64 .. jh*64+63
    bool active = (pairIdx < nA);
    int pair = active ? g_active[pairIdx] : g_inactive[pairIdx - nA];
    int b = pair >> 7, i = pair & 127;
    float* outBase = out + (((size_t)(b * LL + i)) * LL + jh * 64) * TWO_D;

    if (!active) {
        float4 z = make_float4(0.f, 0.f, 0.f, 0.f);
        float4* o4 = (float4*)outBase;
        #pragma unroll
        for (int u = 0; u < 32; u++) o4[t + u * NT] = z;
        return;
    }

    extern __shared__ char smc[];
    uint32_t smb = (uint32_t)__cvta_generic_to_shared(smc);

    __nv_bfloat16* sPhi = (__nv_bfloat16*)(smc + OB_PHI);
    __nv_bfloat16* sPlo = (__nv_bfloat16*)(smc + OB_PLO);
    float* sG1  = (float*)(smc + OB_G1);
    float* sG1q = (float*)(smc + OB_G1Q);
    float* sW   = (float*)(smc + OB_W);
    float* sBi  = (float*)(smc + OB_BI);
    float* sST1 = (float*)(smc + OB_ST1);
    float* sST2 = (float*)(smc + OB_ST2);
    float* sMu  = (float*)(smc + OB_MU);
    float* sRs  = (float*)(smc + OB_RS);

    const float* G   = g_gram + (size_t)b * 4 * LL * LL;
    const float* G2  = G + 1 * LL * LL;   // 0.5*V.V^T
    const float* G2q = G + 3 * LL * LL;   // 0.5*V.Q^T

    int warp = t >> 5, lane = t & 31;
    int g  = lane >> 2;      // 0..7
    int tq = lane & 3;       // 0..3
    int jg     = warp >> 2;         // 0..1 -> 32 local j rows
    int dgroup = warp & 3;          // 0..3 -> 16 d cols within 64-d quarter
    int mbase = jg * 32;            // local row base

    // ldmatrix lane addressing (mat = lane>>3, mr = lane&7)
    int mat = lane >> 3, mr = lane & 7;
    uint32_t aAddrH = smb + OB_PHI +
        (uint32_t)(((mbase + (mat & 1) * 8 + mr) * PSTR + (mat >> 1) * 8) * 2);
    uint32_t aAddrL = aAddrH + (OB_PLO - OB_PHI);
    uint32_t bAddr0 = smb + OB_V +
        (uint32_t)((((mat & 1) * 8 + mr) * VSTR + dgroup * 16 + (mat >> 1) * 8) * 2);

    if (t < 128) {
        sG1[t]  = G[i * LL + t];                 // masked 0.5*q_i . v_k
        sG1q[t] = G[2 * LL * LL + i * LL + t];   // masked 0.5*q_i . q_k
    }
    #pragma unroll
    for (int u = 0; u < 2; u++) {
        sW[t + u * NT]  = nw[t + u * NT];
        sBi[t + u * NT] = nb[t + u * NT];
    }

    // cp.async tile load: [128 k][64 d] bf16 x 2 planes into buffer `buf`.
    auto load_tile_async = [&](int tensor, int dbase, int buf) {
        const __nv_bfloat16* baseH =
            g_bf + (size_t)((b * 2 + tensor) * 2) * (LL * DD);
        const __nv_bfloat16* baseL = baseH + LL * DD;
        uint32_t dbuf = smb + OB_V + (uint32_t)(buf * VBUF);
        #pragma unroll
        for (int u = 0; u < 4; u++) {
            int idx = t + u * NT;            // 0..1023
            int k = idx >> 3, c = idx & 7;   // row, 16B chunk
            uint32_t dofs = (uint32_t)(k * (VSTR * 2) + c * 16);
            cp16(dbuf + dofs,       baseH + k * DD + dbase + c * 8);
            cp16(dbuf + VPL + dofs, baseL + k * DD + dbase + c * 8);
        }
        CP_COMMIT();
    };

    // softmax over this CTA's 64 j rows (global row = jh*64 + jj)
    auto softmax_side = [&](const float* Grow, const float* g1) {
        for (int jj = warp; jj < 64; jj += 8) {
            const float* r = Grow + (jh * 64 + jj) * LL;
            float s0 = g1[lane]      + r[lane];
            float s1 = g1[lane + 32] + r[lane + 32];
            float s2 = g1[lane + 64] + r[lane + 64];
            float s3 = g1[lane + 96] + r[lane + 96];
            float m = fmaxf(fmaxf(s0, s1), fmaxf(s2, s3));
            #pragma unroll
            for (int o = 16; o; o >>= 1) m = fmaxf(m, __shfl_xor_sync(0xffffffffu, m, o));
            float e0 = __expf(s0 - m), e1 = __expf(s1 - m);
            float e2 = __expf(s2 - m), e3 = __expf(s3 - m);
            float su = e0 + e1 + e2 + e3;
            #pragma unroll
            for (int o = 16; o; o >>= 1) su += __shfl_xor_sync(0xffffffffu, su, o);
            float inv = 1.0f / su;
            float vals[4] = {e0 * inv, e1 * inv, e2 * inv, e3 * inv};
            #pragma unroll
            for (int c = 0; c < 4; c++) {
                int k = lane + c * 32;
                float x = vals[c];
                __nv_bfloat16 h = __float2bfloat16(x);
                __nv_bfloat16 l = __float2bfloat16(x - __bfloat162float(h));
                sPhi[jj * PSTR + k] = h;
                sPlo[jj * PSTR + k] = l;
            }
        }
    };

    // ---- prologue: async tile0 -> buf0, softmax side 0 under its flight ----
    load_tile_async(0, 0, 0);
    __syncthreads();                 // sG1/sG1q/sW/sBi visible
    softmax_side(G2, sG1);
    CP_WAIT0();
    __syncthreads();

    float ls1[4] = {}, ls2[4] = {};

    // ---- 8 macro-iterations: (side, d-quarter) over 64j x 64d each ----
    #pragma unroll 1
    for (int mi = 0; mi < 8; mi++) {
        int s  = mi >> 2;
        int dq = mi & 3;

        // issue next tile into the ALTERNATE buffer before compute
        if (mi < 7) {
            int nx = mi + 1;
            load_tile_async(nx >> 2, (nx & 3) * 64, nx & 1);
        }

        // ---- MMA: warp tile 32j x 16d, k = 128, from buf mi&1 ----
        uint32_t bBase = bAddr0 + (uint32_t)((mi & 1) * VBUF);
        float acc[2][2][4] = {};
        #pragma unroll
        for (int kt = 0; kt < 8; kt++) {
            uint32_t ah0[4], ah1[4], al0[4], al1[4], bh[4], bl[4];
            uint32_t ka = (uint32_t)(kt * 32);
            uint32_t kb = (uint32_t)(kt * 16 * VSTR * 2);
            ldsm_x4(ah0, aAddrH + ka);
            ldsm_x4(ah1, aAddrH + 16 * PSTR * 2 + ka);
            ldsm_x4(al0, aAddrL + ka);
            ldsm_x4(al1, aAddrL + 16 * PSTR * 2 + ka);
            ldsm_x4_t(bh, bBase + kb);
            ldsm_x4_t(bl, bBase + VPL + kb);
            // hi*hi
            mma_bf16(acc[0][0], ah0, bh[0], bh[1]);
            mma_bf16(acc[0][1], ah0, bh[2], bh[3]);
            mma_bf16(acc[1][0], ah1, bh[0], bh[1]);
            mma_bf16(acc[1][1], ah1, bh[2], bh[3]);
            // hi*lo
            mma_bf16(acc[0][0], ah0, bl[0], bl[1]);
            mma_bf16(acc[0][1], ah0, bl[2], bl[3]);
            mma_bf16(acc[1][0], ah1, bl[0], bl[1]);
            mma_bf16(acc[1][1], ah1, bl[2], bl[3]);
            // lo*hi
            mma_bf16(acc[0][0], al0, bh[0], bh[1]);
            mma_bf16(acc[0][1], al0, bh[2], bh[3]);
            mma_bf16(acc[1][0], al1, bh[0], bh[1]);
            mma_bf16(acc[1][1], al1, bh[2], bh[3]);
        }

        // ---- store raw output + accumulate LN stats ----
        int colb = s * 256 + dq * 64 + dgroup * 16;
        #pragma unroll
        for (int mt = 0; mt < 2; mt++)
            #pragma unroll
            for (int nt = 0; nt < 2; nt++) {
                const float* a4 = acc[mt][nt];
                int r0 = mbase + mt * 16 + g;           // local row
                int c0 = colb + nt * 8 + tq * 2;
                *(float2*)&outBase[(size_t)r0 * TWO_D + c0] =
                    make_float2(a4[0], a4[1]);
                *(float2*)&outBase[(size_t)(r0 + 8) * TWO_D + c0] =
                    make_float2(a4[2], a4[3]);
                ls1[mt * 2 + 0] += a4[0] + a4[1];
                ls2[mt * 2 + 0] = fmaf(a4[0], a4[0], fmaf(a4[1], a4[1], ls2[mt * 2 + 0]));
                ls1[mt * 2 + 1] += a4[2] + a4[3];
                ls2[mt * 2 + 1] = fmaf(a4[2], a4[2], fmaf(a4[3], a4[3], ls2[mt * 2 + 1]));
            }

        // side-1 softmax: after all side-0 P reads (barrier), while the
        // next tile's cp.async is still in flight.
        if (mi == 3) {
            __syncthreads();
            softmax_side(G2q, sG1q);
        }

        CP_WAIT0();               // next tile landed (no-op cost if done)
        __syncthreads();          // all warps: tile ready / buffers reusable
    }

    // ---- LN stats: shfl-reduce across quad lanes, then smem reduce ----
    #pragma unroll
    for (int ss = 0; ss < 4; ss++) {
        float v1 = ls1[ss], v2 = ls2[ss];
        v1 += __shfl_xor_sync(0xffffffffu, v1, 1);
        v1 += __shfl_xor_sync(0xffffffffu, v1, 2);
        v2 += __shfl_xor_sync(0xffffffffu, v2, 1);
        v2 += __shfl_xor_sync(0xffffffffu, v2, 2);
        if (tq == 0) {
            int row = mbase + (ss >> 1) * 16 + (ss & 1) * 8 + g;   // local
            sST1[row * 4 + dgroup] = v1;
            sST2[row * 4 + dgroup] = v2;
        }
    }
    __syncthreads();
    if (t < 64) {
        float a1 = sST1[t * 4 + 0] + sST1[t * 4 + 1] + sST1[t * 4 + 2] + sST1[t * 4 + 3];
        float a2 = sST2[t * 4 + 0] + sST2[t * 4 + 1] + sST2[t * 4 + 2] + sST2[t * 4 + 3];
        float mu  = a1 * (1.0f / 512.0f);
        float var = a2 * (1.0f / 512.0f) - mu * mu;
        sMu[t] = mu;
        sRs[t] = rsqrtf(var + 1e-5f);
    }
    __syncthreads();

    // ---- Phase C: LayerNorm in place (region is L2-hot) ----
    int jr = t >> 2, part = t & 3;                  // local row, 4 thr/row
    float mu = sMu[jr], rs = sRs[jr];
    float* orow = outBase + (size_t)jr * TWO_D;
    #pragma unroll 4
    for (int itc = 0; itc < 32; itc++) {
        int idx4 = itc * 4 + part;       // 0..127
        int d = idx4 * 4;
        float4 x = *(float4*)&orow[d];
        x.x = (x.x - mu) * rs * sW[d + 0] + sBi[d + 0];
        x.y = (x.y - mu) * rs * sW[d + 1] + sBi[d + 1];
        x.z = (x.z - mu) * rs * sW[d + 2] + sBi[d + 2];
        x.w = (x.w - mu) * rs * sW[d + 3] + sBi[d + 3];
        *(float4*)&orow[d] = x;
    }
}

// ---------------------------------------------------------------------------
extern "C" void kernel_launch(void* const* d_in, const int* in_sizes, int n_in,
                              void* d_out, int out_size)
{
    const float* q    = (const float*)d_in[0];
    const float* v    = (const float*)d_in[1];
    const int*   mask = (const int*)d_in[2];
    const float* nw   = (const float*)d_in[3];
    const float* nb   = (const float*)d_in[4];
    float* out = (float*)d_out;

    gram_kernel<<<dim3(32, BB), 256>>>(q, v, mask);

    cudaFuncSetAttribute(attn_kernel,
                         cudaFuncAttributeMaxDynamicSharedMemorySize, SMEM_BYTES);
    attn_kernel<<<2 * BB * LL, NT, SMEM_BYTES>>>(q, v, nw, nb, out);
}

// round 16
// speedup vs baseline: 1.1570x; 1.0533x over previous
#include <cuda_runtime.h>
#include <cuda_bf16.h>
#include <cstdint>

#define BB 4
#define LL 128
#define DD 256
#define TWO_D 512

// Gram scratch: [b][type][r][k], types: 0=0.5*Q.V^T(+mask), 1=0.5*V.V^T,
//                                        2=0.5*Q.Q^T(+mask), 3=0.5*V.Q^T
__device__ float g_gram[BB * 4 * LL * LL];

// Pre-split bf16 planes of V and Q: [b][tensor(0=V,1=Q)][plane(0=hi,1=lo)][k][d]
__device__ __nv_bfloat16 g_bf[BB * 2 * 2 * LL * DD];

// Mask compaction lists: pair = b*128 + i
__device__ int g_active[BB * LL];
__device__ int g_inactive[BB * LL];
__device__ int g_nactive;

// ---------------------------------------------------------------------------
// Kernel 1: Gram matrices. grid (32, B). 256 threads. 16 rows per block.
// Every block also converts its share of V/Q into bf16 hi/lo planes.
// Block (0,0) additionally compacts the mask.
// ---------------------------------------------------------------------------
__global__ __launch_bounds__(256) void gram_kernel(
    const float* __restrict__ Q, const float* __restrict__ V,
    const int* __restrict__ mask)
{
    int t = threadIdx.x;

    if (blockIdx.x == 0 && blockIdx.y == 0) {
        __shared__ int cA, cI;
        if (t == 0) { cA = 0; cI = 0; }
        __syncthreads();
        for (int e = t; e < BB * LL; e += 256) {
            if (mask[e]) g_active[atomicAdd(&cA, 1)] = e;
            else         g_inactive[atomicAdd(&cI, 1)] = e;
        }
        __syncthreads();
        if (t == 0) g_nactive = cA;
    }

    // ---- bf16 plane conversion: 128 blocks x 2048 elements ----
    {
        int blk = blockIdx.y * 32 + blockIdx.x;      // 0..127
        #pragma unroll
        for (int u = 0; u < 8; u++) {
            int e = blk * 2048 + t + u * 256;        // 0..262143
            int tb    = e >> 15;                     // 0..7 = b*2 + tensor
            int inner = e & 32767;                   // k*256 + d
            int bb = tb >> 1, tensor = tb & 1;
            const float* src = (tensor ? Q : V) + (size_t)bb * LL * DD;
            float x = src[inner];
            __nv_bfloat16 h = __float2bfloat16(x);
            __nv_bfloat16 l = __float2bfloat16(x - __bfloat162float(h));
            size_t base = (size_t)(tb * 2) * (LL * DD);
            g_bf[base + inner]           = h;
            g_bf[base + LL * DD + inner] = l;
        }
    }

    int b    = blockIdx.y;
    int type = blockIdx.x >> 3;       // 0..3
    int rq   = blockIdx.x & 7;        // 0..7
    const float* A  = ((type & 1) ? V : Q) + (size_t)b * LL * DD;
    const float* Bm = ((type < 2) ? V : Q) + (size_t)b * LL * DD;
    int r0 = rq * 16;

    __shared__ float sA[16 * 65];
    __shared__ float sB[128 * 65];

    float acc[2][4] = {};

    for (int dc = 0; dc < DD; dc += 64) {
        #pragma unroll
        for (int u = 0; u < 32; u++) {
            int idx = t + u * 256;               // 0..8191
            int r = idx >> 6, d = idx & 63;
            sB[r * 65 + d] = Bm[r * DD + dc + d];
        }
        #pragma unroll
        for (int u = 0; u < 4; u++) {
            int idx = t + u * 256;               // 0..1023
            int r = idx >> 6, d = idx & 63;
            sA[r * 65 + d] = A[(r0 + r) * DD + dc + d];
        }
        __syncthreads();

        // k = kg + c*32: consecutive lanes hit consecutive rows (stride 65
        // words, odd) -> conflict-free, vs old kg*4+c (stride 260 = 4-way).
        int rg = t >> 5, kg = t & 31;
        const float* sAr = sA + rg * 2 * 65;
        const float* sBr = sB + kg * 65;
        #pragma unroll 8
        for (int d = 0; d < 64; d++) {
            float av[2], bv[4];
            #pragma unroll
            for (int a = 0; a < 2; a++) av[a] = sAr[a * 65 + d];
            #pragma unroll
            for (int c = 0; c < 4; c++) bv[c] = sBr[c * 32 * 65 + d];
            #pragma unroll
            for (int a = 0; a < 2; a++)
                #pragma unroll
                for (int c = 0; c < 4; c++)
                    acc[a][c] = fmaf(av[a], bv[c], acc[a][c]);
        }
        __syncthreads();
    }

    int rg = t >> 5, kg = t & 31;
    float* G = g_gram + (size_t)(b * 4 + type) * LL * LL;
    bool doMask = (type == 0) || (type == 2);
    #pragma unroll
    for (int a = 0; a < 2; a++) {
        #pragma unroll
        for (int c = 0; c < 4; c++) {
            int k = kg + c * 32;
            float val = 0.5f * acc[a][c];
            if (doMask && mask[b * LL + k] == 0) val = -1e30f;
            G[(r0 + rg * 2 + a) * LL + k] = val;
        }
    }
}

// ---------------------------------------------------------------------------
// mma.sync / ldmatrix / cp.async helpers
// ---------------------------------------------------------------------------
__device__ __forceinline__ void mma_bf16(float* c, const uint32_t* a,
                                         uint32_t b0, uint32_t b1)
{
    asm volatile(
        "mma.sync.aligned.m16n8k16.row.col.f32.bf16.bf16.f32 "
        "{%0,%1,%2,%3}, {%4,%5,%6,%7}, {%8,%9}, {%0,%1,%2,%3};"
        : "+f"(c[0]), "+f"(c[1]), "+f"(c[2]), "+f"(c[3])
        : "r"(a[0]), "r"(a[1]), "r"(a[2]), "r"(a[3]), "r"(b0), "r"(b1));
}
__device__ __forceinline__ void ldsm_x4(uint32_t* r, uint32_t addr)
{
    asm volatile("ldmatrix.sync.aligned.m8n8.x4.shared.b16 {%0,%1,%2,%3}, [%4];"
        : "=r"(r[0]), "=r"(r[1]), "=r"(r[2]), "=r"(r[3]) : "r"(addr));
}
__device__ __forceinline__ void ldsm_x4_t(uint32_t* r, uint32_t addr)
{
    asm volatile("ldmatrix.sync.aligned.m8n8.x4.trans.shared.b16 {%0,%1,%2,%3}, [%4];"
        : "=r"(r[0]), "=r"(r[1]), "=r"(r[2]), "=r"(r[3]) : "r"(addr));
}
__device__ __forceinline__ void cp16(uint32_t dst, const void* src)
{
    asm volatile("cp.async.cg.shared.global [%0], [%1], 16;"
                 :: "r"(dst), "l"(src) : "memory");
}
#define CP_COMMIT() asm volatile("cp.async.commit_group;" ::: "memory")
#define CP_WAIT0()  asm volatile("cp.async.wait_group 0;" ::: "memory")

// ---------------------------------------------------------------------------
// Kernel 2: attention via mma.sync bf16x3 + LayerNorm.
// TWO blocks per (b,i) (j-halves of 64 rows), 256 threads, 2 CTAs/SM.
// Double-buffered V tiles (cp.async) AND software-pipelined ldmatrix
// fragments (ping-pong register sets): LDSM of kt+1 issues before the
// 12 MMAs of kt, so neither gmem nor smem latency is exposed.
// P planes [64 j][136 k] bf16 (hi/lo); V tile [128 k][72 d] bf16 K-major.
// ---------------------------------------------------------------------------
#define NT 256
#define PSTR 136
#define VSTR 72
// byte offsets in dynamic smem
#define OB_PHI   0                     // 64*136*2 = 17408
#define OB_PLO   17408                 // 17408
#define OB_V     34816                 // 2 bufs x (2 planes x 18432) = 73728
#define VPL      18432                 // bytes per V plane
#define VBUF     36864                 // bytes per V buffer (hi+lo)
#define OB_G1    108544                // 128 f
#define OB_G1Q   109056                // 128 f
#define OB_W     109568                // 512 f
#define OB_BI    111616                // 512 f
// stats overlay the V region (dead by epilogue)
#define OB_ST1   OB_V                  // 64*4 f
#define OB_ST2   (OB_V + 1024)         // 64*4 f
#define OB_MU    (OB_V + 2048)         // 64 f
#define OB_RS    (OB_V + 2304)         // 64 f
#define SMEM_BYTES 113664              // x2 CTAs = 227328 <= 233472

__global__ __launch_bounds__(NT, 2) void attn_kernel(
    const float* __restrict__ Q, const float* __restrict__ V,
    const float* __restrict__ nw, const float* __restrict__ nb,
    float* __restrict__ out)
{
    int bid = blockIdx.x;
    int t   = threadIdx.x;
    int nA  = g_nactive;
    int pairIdx = bid >> 1;
    int jh      = bid & 1;            // j half: rows jh*64 .. jh*64+63
    bool active = (pairIdx < nA);
    int pair = active ? g_active[pairIdx] : g_inactive[pairIdx - nA];
    int b = pair >> 7, i = pair & 127;
    float* outBase = out + (((size_t)(b * LL + i)) * LL + jh * 64) * TWO_D;

    if (!active) {
        float4 z = make_float4(0.f, 0.f, 0.f, 0.f);
        float4* o4 = (float4*)outBase;
        #pragma unroll
        for (int u = 0; u < 32; u++) o4[t + u * NT] = z;
        return;
    }

    extern __shared__ char smc[];
    uint32_t smb = (uint32_t)__cvta_generic_to_shared(smc);

    __nv_bfloat16* sPhi = (__nv_bfloat16*)(smc + OB_PHI);
    __nv_bfloat16* sPlo = (__nv_bfloat16*)(smc + OB_PLO);
    float* sG1  = (float*)(smc + OB_G1);
    float* sG1q = (float*)(smc + OB_G1Q);
    float* sW   = (float*)(smc + OB_W);
    float* sBi  = (float*)(smc + OB_BI);
    float* sST1 = (float*)(smc + OB_ST1);
    float* sST2 = (float*)(smc + OB_ST2);
    float* sMu  = (float*)(smc + OB_MU);
    float* sRs  = (float*)(smc + OB_RS);

    const float* G   = g_gram + (size_t)b * 4 * LL * LL;
    const float* G2  = G + 1 * LL * LL;   // 0.5*V.V^T
    const float* G2q = G + 3 * LL * LL;   // 0.5*V.Q^T

    int warp = t >> 5, lane = t & 31;
    int g  = lane >> 2;      // 0..7
    int tq = lane & 3;       // 0..3
    int jg     = warp >> 2;         // 0..1 -> 32 local j rows
    int dgroup = warp & 3;          // 0..3 -> 16 d cols within 64-d quarter
    int mbase = jg * 32;            // local row base

    // ldmatrix lane addressing (mat = lane>>3, mr = lane&7)
    int mat = lane >> 3, mr = lane & 7;
    uint32_t aAddrH = smb + OB_PHI +
        (uint32_t)(((mbase + (mat & 1) * 8 + mr) * PSTR + (mat >> 1) * 8) * 2);
    uint32_t aAddrL = aAddrH + (OB_PLO - OB_PHI);
    uint32_t bAddr0 = smb + OB_V +
        (uint32_t)((((mat & 1) * 8 + mr) * VSTR + dgroup * 16 + (mat >> 1) * 8) * 2);

    if (t < 128) {
        sG1[t]  = G[i * LL + t];                 // masked 0.5*q_i . v_k
        sG1q[t] = G[2 * LL * LL + i * LL + t];   // masked 0.5*q_i . q_k
    }
    #pragma unroll
    for (int u = 0; u < 2; u++) {
        sW[t + u * NT]  = nw[t + u * NT];
        sBi[t + u * NT] = nb[t + u * NT];
    }

    // cp.async tile load: [128 k][64 d] bf16 x 2 planes into buffer `buf`.
    auto load_tile_async = [&](int tensor, int dbase, int buf) {
        const __nv_bfloat16* baseH =
            g_bf + (size_t)((b * 2 + tensor) * 2) * (LL * DD);
        const __nv_bfloat16* baseL = baseH + LL * DD;
        uint32_t dbuf = smb + OB_V + (uint32_t)(buf * VBUF);
        #pragma unroll
        for (int u = 0; u < 4; u++) {
            int idx = t + u * NT;            // 0..1023
            int k = idx >> 3, c = idx & 7;   // row, 16B chunk
            uint32_t dofs = (uint32_t)(k * (VSTR * 2) + c * 16);
            cp16(dbuf + dofs,       baseH + k * DD + dbase + c * 8);
            cp16(dbuf + VPL + dofs, baseL + k * DD + dbase + c * 8);
        }
        CP_COMMIT();
    };

    // fragment loads for one kt step (6 ldmatrix.x4)
    auto load_frags = [&](int kt, uint32_t* fa, uint32_t* fb, uint32_t bBase) {
        uint32_t ka = (uint32_t)(kt * 32);
        uint32_t kb = (uint32_t)(kt * 16 * VSTR * 2);
        ldsm_x4(fa + 0,  aAddrH + ka);
        ldsm_x4(fa + 4,  aAddrH + 16 * PSTR * 2 + ka);
        ldsm_x4(fa + 8,  aAddrL + ka);
        ldsm_x4(fa + 12, aAddrL + 16 * PSTR * 2 + ka);
        ldsm_x4_t(fb + 0, bBase + kb);
        ldsm_x4_t(fb + 4, bBase + VPL + kb);
    };

    // softmax over this CTA's 64 j rows (global row = jh*64 + jj)
    auto softmax_side = [&](const float* Grow, const float* g1) {
        for (int jj = warp; jj < 64; jj += 8) {
            const float* r = Grow + (jh * 64 + jj) * LL;
            float s0 = g1[lane]      + r[lane];
            float s1 = g1[lane + 32] + r[lane + 32];
            float s2 = g1[lane + 64] + r[lane + 64];
            float s3 = g1[lane + 96] + r[lane + 96];
            float m = fmaxf(fmaxf(s0, s1), fmaxf(s2, s3));
            #pragma unroll
            for (int o = 16; o; o >>= 1) m = fmaxf(m, __shfl_xor_sync(0xffffffffu, m, o));
            float e0 = __expf(s0 - m), e1 = __expf(s1 - m);
            float e2 = __expf(s2 - m), e3 = __expf(s3 - m);
            float su = e0 + e1 + e2 + e3;
            #pragma unroll
            for (int o = 16; o; o >>= 1) su += __shfl_xor_sync(0xffffffffu, su, o);
            float inv = 1.0f / su;
            float vals[4] = {e0 * inv, e1 * inv, e2 * inv, e3 * inv};
            #pragma unroll
            for (int c = 0; c < 4; c++) {
                int k = lane + c * 32;
                float x = vals[c];
                __nv_bfloat16 h = __float2bfloat16(x);
                __nv_bfloat16 l = __float2bfloat16(x - __bfloat162float(h));
                sPhi[jj * PSTR + k] = h;
                sPlo[jj * PSTR + k] = l;
            }
        }
    };

    // ---- prologue: async tile0 -> buf0, softmax side 0 under its flight ----
    load_tile_async(0, 0, 0);
    __syncthreads();                 // sG1/sG1q/sW/sBi visible
    softmax_side(G2, sG1);
    CP_WAIT0();
    __syncthreads();

    float ls1[4] = {}, ls2[4] = {};

    // ---- 8 macro-iterations: (side, d-quarter) over 64j x 64d each ----
    #pragma unroll 1
    for (int mi = 0; mi < 8; mi++) {
        int s  = mi >> 2;
        int dq = mi & 3;

        // issue next tile into the ALTERNATE buffer before compute
        if (mi < 7) {
            int nx = mi + 1;
            load_tile_async(nx >> 2, (nx & 3) * 64, nx & 1);
        }

        // ---- MMA: warp tile 32j x 16d, k = 128, from buf mi&1 ----
        // Fragments software-pipelined: kt+1's LDSMs issue before kt's MMAs.
        uint32_t bBase = bAddr0 + (uint32_t)((mi & 1) * VBUF);
        float acc[2][2][4] = {};
        uint32_t fA[2][16], fB[2][8];
        load_frags(0, fA[0], fB[0], bBase);
        #pragma unroll
        for (int kt = 0; kt < 8; kt++) {
            int cur = kt & 1;
            if (kt < 7) load_frags(kt + 1, fA[cur ^ 1], fB[cur ^ 1], bBase);
            const uint32_t* a  = fA[cur];
            const uint32_t* bq = fB[cur];
            // hi*hi
            mma_bf16(acc[0][0], a + 0, bq[0], bq[1]);
            mma_bf16(acc[0][1], a + 0, bq[2], bq[3]);
            mma_bf16(acc[1][0], a + 4, bq[0], bq[1]);
            mma_bf16(acc[1][1], a + 4, bq[2], bq[3]);
            // hi*lo
            mma_bf16(acc[0][0], a + 0, bq[4], bq[5]);
            mma_bf16(acc[0][1], a + 0, bq[6], bq[7]);
            mma_bf16(acc[1][0], a + 4, bq[4], bq[5]);
            mma_bf16(acc[1][1], a + 4, bq[6], bq[7]);
            // lo*hi
            mma_bf16(acc[0][0], a + 8,  bq[0], bq[1]);
            mma_bf16(acc[0][1], a + 8,  bq[2], bq[3]);
            mma_bf16(acc[1][0], a + 12, bq[0], bq[1]);
            mma_bf16(acc[1][1], a + 12, bq[2], bq[3]);
        }

        // ---- store raw output + accumulate LN stats ----
        int colb = s * 256 + dq * 64 + dgroup * 16;
        #pragma unroll
        for (int mt = 0; mt < 2; mt++)
            #pragma unroll
            for (int nt = 0; nt < 2; nt++) {
                const float* a4 = acc[mt][nt];
                int r0 = mbase + mt * 16 + g;           // local row
                int c0 = colb + nt * 8 + tq * 2;
                *(float2*)&outBase[(size_t)r0 * TWO_D + c0] =
                    make_float2(a4[0], a4[1]);
                *(float2*)&outBase[(size_t)(r0 + 8) * TWO_D + c0] =
                    make_float2(a4[2], a4[3]);
                ls1[mt * 2 + 0] += a4[0] + a4[1];
                ls2[mt * 2 + 0] = fmaf(a4[0], a4[0], fmaf(a4[1], a4[1], ls2[mt * 2 + 0]));
                ls1[mt * 2 + 1] += a4[2] + a4[3];
                ls2[mt * 2 + 1] = fmaf(a4[2], a4[2], fmaf(a4[3], a4[3], ls2[mt * 2 + 1]));
            }

        // side-1 softmax: after all side-0 P reads (barrier), while the
        // next tile's cp.async is still in flight.
        if (mi == 3) {
            __syncthreads();
            softmax_side(G2q, sG1q);
        }

        CP_WAIT0();               // next tile landed (no-op cost if done)
        __syncthreads();          // all warps: tile ready / buffers reusable
    }

    // ---- LN stats: shfl-reduce across quad lanes, then smem reduce ----
    #pragma unroll
    for (int ss = 0; ss < 4; ss++) {
        float v1 = ls1[ss], v2 = ls2[ss];
        v1 += __shfl_xor_sync(0xffffffffu, v1, 1);
        v1 += __shfl_xor_sync(0xffffffffu, v1, 2);
        v2 += __shfl_xor_sync(0xffffffffu, v2, 1);
        v2 += __shfl_xor_sync(0xffffffffu, v2, 2);
        if (tq == 0) {
            int row = mbase + (ss >> 1) * 16 + (ss & 1) * 8 + g;   // local
            sST1[row * 4 + dgroup] = v1;
            sST2[row * 4 + dgroup] = v2;
        }
    }
    __syncthreads();
    if (t < 64) {
        float a1 = sST1[t * 4 + 0] + sST1[t * 4 + 1] + sST1[t * 4 + 2] + sST1[t * 4 + 3];
        float a2 = sST2[t * 4 + 0] + sST2[t * 4 + 1] + sST2[t * 4 + 2] + sST2[t * 4 + 3];
        float mu  = a1 * (1.0f / 512.0f);
        float var = a2 * (1.0f / 512.0f) - mu * mu;
        sMu[t] = mu;
        sRs[t] = rsqrtf(var + 1e-5f);
    }
    __syncthreads();

    // ---- Phase C: LayerNorm in place (region is L2-hot) ----
    int jr = t >> 2, part = t & 3;                  // local row, 4 thr/row
    float mu = sMu[jr], rs = sRs[jr];
    float* orow = outBase + (size_t)jr * TWO_D;
    #pragma unroll 4
    for (int itc = 0; itc < 32; itc++) {
        int idx4 = itc * 4 + part;       // 0..127
        int d = idx4 * 4;
        float4 x = *(float4*)&orow[d];
        x.x = (x.x - mu) * rs * sW[d + 0] + sBi[d + 0];
        x.y = (x.y - mu) * rs * sW[d + 1] + sBi[d + 1];
        x.z = (x.z - mu) * rs * sW[d + 2] + sBi[d + 2];
        x.w = (x.w - mu) * rs * sW[d + 3] + sBi[d + 3];
        *(float4*)&orow[d] = x;
    }
}

// ---------------------------------------------------------------------------
extern "C" void kernel_launch(void* const* d_in, const int* in_sizes, int n_in,
                              void* d_out, int out_size)
{
    const float* q    = (const float*)d_in[0];
    const float* v    = (const float*)d_in[1];
    const int*   mask = (const int*)d_in[2];
    const float* nw   = (const float*)d_in[3];
    const float* nb   = (const float*)d_in[4];
    float* out = (float*)d_out;

    gram_kernel<<<dim3(32, BB), 256>>>(q, v, mask);

    cudaFuncSetAttribute(attn_kernel,
                         cudaFuncAttributeMaxDynamicSharedMemorySize, SMEM_BYTES);
    attn_kernel<<<2 * BB * LL, NT, SMEM_BYTES>>>(q, v, nw, nb, out);
}

// round 17
// speedup vs baseline: 1.1589x; 1.0017x over previous
#include <cuda_runtime.h>
#include <cuda_bf16.h>
#include <cstdint>

#define BB 4
#define LL 128
#define DD 256
#define TWO_D 512

// Gram scratch (k-compacted columns): [b][type][r][kc]
// types: 0=0.5*Q.V^T, 1=0.5*V.V^T, 2=0.5*Q.Q^T, 3=0.5*V.Q^T
__device__ float g_gram[BB * 4 * LL * LL];

// Pre-split bf16 planes of V and Q, k-compacted rows:
// [b][tensor(0=V,1=Q)][plane(0=hi,1=lo)][kc][d]   (tail rows stay zero)
__device__ __nv_bfloat16 g_bf[BB * 2 * 2 * LL * DD];

// per-batch active-k count
__device__ int g_nk[BB];

// ---------------------------------------------------------------------------
// Kernel 1: Gram matrices (k-compacted) + bf16 plane conversion.
// grid (32, B). 256 threads. 16 rows per block.
// ---------------------------------------------------------------------------
__global__ __launch_bounds__(256) void gram_kernel(
    const float* __restrict__ Q, const float* __restrict__ V,
    const int* __restrict__ mask)
{
    int t = threadIdx.x;
    int b = blockIdx.y;

    // per-batch compacted column positions (redundantly computed per block)
    __shared__ int pos[LL];
    __shared__ int snk;
    if (t == 0) {
        int c = 0;
        for (int k = 0; k < LL; k++)
            pos[k] = mask[b * LL + k] ? c++ : -1;
        snk = c;
        if (blockIdx.x == 0) g_nk[b] = c;
    }
    __syncthreads();

    // ---- bf16 plane conversion (compacted rows): 32 blocks x 2048 elems ----
    {
        int base = blockIdx.x * 2048;
        #pragma unroll
        for (int u = 0; u < 8; u++) {
            int e = base + t + u * 256;              // 0..65535 within batch
            int tensor = e >> 15;                    // 0=V, 1=Q
            int k = (e >> 8) & 127;
            int d = e & 255;
            int kc = pos[k];
            if (kc >= 0) {
                const float* src = (tensor ? Q : V) + (size_t)b * LL * DD;
                float x = src[k * DD + d];
                __nv_bfloat16 h = __float2bfloat16(x);
                __nv_bfloat16 l = __float2bfloat16(x - __bfloat162float(h));
                size_t pb = (size_t)((b * 2 + tensor) * 2) * (LL * DD);
                g_bf[pb + kc * DD + d]           = h;
                g_bf[pb + LL * DD + kc * DD + d] = l;
            }
        }
    }

    int type = blockIdx.x >> 3;       // 0..3
    int rq   = blockIdx.x & 7;        // 0..7
    const float* A  = ((type & 1) ? V : Q) + (size_t)b * LL * DD;
    const float* Bm = ((type < 2) ? V : Q) + (size_t)b * LL * DD;
    int r0 = rq * 16;

    __shared__ float sA[16 * 65];
    __shared__ float sB[128 * 65];

    float acc[2][4] = {};

    for (int dc = 0; dc < DD; dc += 64) {
        #pragma unroll
        for (int u = 0; u < 32; u++) {
            int idx = t + u * 256;               // 0..8191
            int r = idx >> 6, d = idx & 63;
            sB[r * 65 + d] = Bm[r * DD + dc + d];
        }
        #pragma unroll
        for (int u = 0; u < 4; u++) {
            int idx = t + u * 256;               // 0..1023
            int r = idx >> 6, d = idx & 63;
            sA[r * 65 + d] = A[(r0 + r) * DD + dc + d];
        }
        __syncthreads();

        int rg = t >> 5, kg = t & 31;
        const float* sAr = sA + rg * 2 * 65;
        const float* sBr = sB + kg * 65;
        #pragma unroll 8
        for (int d = 0; d < 64; d++) {
            float av[2], bv[4];
            #pragma unroll
            for (int a = 0; a < 2; a++) av[a] = sAr[a * 65 + d];
            #pragma unroll
            for (int c = 0; c < 4; c++) bv[c] = sBr[c * 32 * 65 + d];
            #pragma unroll
            for (int a = 0; a < 2; a++)
                #pragma unroll
                for (int c = 0; c < 4; c++)
                    acc[a][c] = fmaf(av[a], bv[c], acc[a][c]);
        }
        __syncthreads();
    }

    // write compacted columns only (no -1e30 masking needed anymore)
    int rg = t >> 5, kg = t & 31;
    float* G = g_gram + (size_t)(b * 4 + type) * LL * LL;
    #pragma unroll
    for (int a = 0; a < 2; a++) {
        #pragma unroll
        for (int c = 0; c < 4; c++) {
            int k = kg + c * 32;
            int kc = pos[k];
            if (kc >= 0)
                G[(r0 + rg * 2 + a) * LL + kc] = 0.5f * acc[a][c];
        }
    }
}

// ---------------------------------------------------------------------------
// mma.sync / ldmatrix / cp.async helpers
// ---------------------------------------------------------------------------
__device__ __forceinline__ void mma_bf16(float* c, const uint32_t* a,
                                         uint32_t b0, uint32_t b1)
{
    asm volatile(
        "mma.sync.aligned.m16n8k16.row.col.f32.bf16.bf16.f32 "
        "{%0,%1,%2,%3}, {%4,%5,%6,%7}, {%8,%9}, {%0,%1,%2,%3};"
        : "+f"(c[0]), "+f"(c[1]), "+f"(c[2]), "+f"(c[3])
        : "r"(a[0]), "r"(a[1]), "r"(a[2]), "r"(a[3]), "r"(b0), "r"(b1));
}
__device__ __forceinline__ void ldsm_x4(uint32_t* r, uint32_t addr)
{
    asm volatile("ldmatrix.sync.aligned.m8n8.x4.shared.b16 {%0,%1,%2,%3}, [%4];"
        : "=r"(r[0]), "=r"(r[1]), "=r"(r[2]), "=r"(r[3]) : "r"(addr));
}
__device__ __forceinline__ void ldsm_x4_t(uint32_t* r, uint32_t addr)
{
    asm volatile("ldmatrix.sync.aligned.m8n8.x4.trans.shared.b16 {%0,%1,%2,%3}, [%4];"
        : "=r"(r[0]), "=r"(r[1]), "=r"(r[2]), "=r"(r[3]) : "r"(addr));
}
__device__ __forceinline__ void cp16(uint32_t dst, const void* src)
{
    asm volatile("cp.async.cg.shared.global [%0], [%1], 16;"
                 :: "r"(dst), "l"(src) : "memory");
}
#define CP_COMMIT() asm volatile("cp.async.commit_group;" ::: "memory")
#define CP_WAIT0()  asm volatile("cp.async.wait_group 0;" ::: "memory")

// ---------------------------------------------------------------------------
// Kernel 2: attention via mma.sync bf16x3 + LayerNorm, K-COMPACTED.
// TWO blocks per (b,i) (j-halves of 64 rows), 256 threads, 2 CTAs/SM.
// kt loop runs ceil(nk/16) (~4.5 avg of 8): MMA/LDSM/loads scale ~0.56x.
// Natural bid order interleaves zero-fill blocks under compute.
// ---------------------------------------------------------------------------
#define NT 256
#define PSTR 136
#define VSTR 72
// byte offsets in dynamic smem
#define OB_PHI   0                     // 64*136*2 = 17408
#define OB_PLO   17408                 // 17408
#define OB_V     34816                 // 2 bufs x (2 planes x 18432) = 73728
#define VPL      18432                 // bytes per V plane
#define VBUF     36864                 // bytes per V buffer (hi+lo)
#define OB_G1    108544                // 128 f
#define OB_G1Q   109056                // 128 f
#define OB_W     109568                // 512 f
#define OB_BI    111616                // 512 f
// stats overlay the V region (dead by epilogue)
#define OB_ST1   OB_V                  // 64*4 f
#define OB_ST2   (OB_V + 1024)         // 64*4 f
#define OB_MU    (OB_V + 2048)         // 64 f
#define OB_RS    (OB_V + 2304)         // 64 f
#define SMEM_BYTES 113664              // x2 CTAs = 227328 <= 233472

__global__ __launch_bounds__(NT, 2) void attn_kernel(
    const float* __restrict__ Q, const float* __restrict__ V,
    const int* __restrict__ mask,
    const float* __restrict__ nw, const float* __restrict__ nb,
    float* __restrict__ out)
{
    int bid = blockIdx.x;
    int t   = threadIdx.x;
    int pair = bid >> 1;
    int jh   = bid & 1;               // j half: rows jh*64 .. jh*64+63
    int b = pair >> 7, i = pair & 127;
    float* outBase = out + (((size_t)(b * LL + i)) * LL + jh * 64) * TWO_D;

    if (mask[pair] == 0) {
        float4 z = make_float4(0.f, 0.f, 0.f, 0.f);
        float4* o4 = (float4*)outBase;
        #pragma unroll
        for (int u = 0; u < 32; u++) o4[t + u * NT] = z;
        return;
    }

    int nk    = g_nk[b];
    int nkt   = (nk + 15) >> 4;       // kt tiles (1..8)
    int nkpad = nkt << 4;

    extern __shared__ char smc[];
    uint32_t smb = (uint32_t)__cvta_generic_to_shared(smc);

    __nv_bfloat16* sPhi = (__nv_bfloat16*)(smc + OB_PHI);
    __nv_bfloat16* sPlo = (__nv_bfloat16*)(smc + OB_PLO);
    float* sG1  = (float*)(smc + OB_G1);
    float* sG1q = (float*)(smc + OB_G1Q);
    float* sW   = (float*)(smc + OB_W);
    float* sBi  = (float*)(smc + OB_BI);
    float* sST1 = (float*)(smc + OB_ST1);
    float* sST2 = (float*)(smc + OB_ST2);
    float* sMu  = (float*)(smc + OB_MU);
    float* sRs  = (float*)(smc + OB_RS);

    const float* G   = g_gram + (size_t)b * 4 * LL * LL;
    const float* G2  = G + 1 * LL * LL;   // 0.5*V.V^T (compacted cols)
    const float* G2q = G + 3 * LL * LL;   // 0.5*V.Q^T (compacted cols)

    int warp = t >> 5, lane = t & 31;
    int g  = lane >> 2;      // 0..7
    int tq = lane & 3;       // 0..3
    int jg     = warp >> 2;         // 0..1 -> 32 local j rows
    int dgroup = warp & 3;          // 0..3 -> 16 d cols within 64-d quarter
    int mbase = jg * 32;            // local row base

    // ldmatrix lane addressing (mat = lane>>3, mr = lane&7)
    int mat = lane >> 3, mr = lane & 7;
    uint32_t aAddrH = smb + OB_PHI +
        (uint32_t)(((mbase + (mat & 1) * 8 + mr) * PSTR + (mat >> 1) * 8) * 2);
    uint32_t aAddrL = aAddrH + (OB_PLO - OB_PHI);
    uint32_t bAddr0 = smb + OB_V +
        (uint32_t)((((mat & 1) * 8 + mr) * VSTR + dgroup * 16 + (mat >> 1) * 8) * 2);

    if (t < 128) {
        sG1[t]  = G[i * LL + t];                 // 0.5*q_i . v_kc
        sG1q[t] = G[2 * LL * LL + i * LL + t];   // 0.5*q_i . q_kc
    }
    #pragma unroll
    for (int u = 0; u < 2; u++) {
        sW[t + u * NT]  = nw[t + u * NT];
        sBi[t + u * NT] = nb[t + u * NT];
    }

    // cp.async tile load: [nkpad k][64 d] bf16 x 2 planes into buffer `buf`.
    auto load_tile_async = [&](int tensor, int dbase, int buf) {
        const __nv_bfloat16* baseH =
            g_bf + (size_t)((b * 2 + tensor) * 2) * (LL * DD);
        const __nv_bfloat16* baseL = baseH + LL * DD;
        uint32_t dbuf = smb + OB_V + (uint32_t)(buf * VBUF);
        #pragma unroll
        for (int u = 0; u < 4; u++) {
            int idx = t + u * NT;            // 0..1023
            int k = idx >> 3, c = idx & 7;   // row, 16B chunk
            if (k < nkpad) {
                uint32_t dofs = (uint32_t)(k * (VSTR * 2) + c * 16);
                cp16(dbuf + dofs,       baseH + k * DD + dbase + c * 8);
                cp16(dbuf + VPL + dofs, baseL + k * DD + dbase + c * 8);
            }
        }
        CP_COMMIT();
    };

    // fragment loads for one kt step (6 ldmatrix.x4)
    auto load_frags = [&](int kt, uint32_t* fa, uint32_t* fb, uint32_t bBase) {
        uint32_t ka = (uint32_t)(kt * 32);
        uint32_t kb = (uint32_t)(kt * 16 * VSTR * 2);
        ldsm_x4(fa + 0,  aAddrH + ka);
        ldsm_x4(fa + 4,  aAddrH + 16 * PSTR * 2 + ka);
        ldsm_x4(fa + 8,  aAddrL + ka);
        ldsm_x4(fa + 12, aAddrL + 16 * PSTR * 2 + ka);
        ldsm_x4_t(fb + 0, bBase + kb);
        ldsm_x4_t(fb + 4, bBase + VPL + kb);
    };

    // softmax over this CTA's 64 j rows; pad lanes (kc >= nk) get -inf -> 0.
    auto softmax_side = [&](const float* Grow, const float* g1) {
        const float NEG = -1e30f;
        for (int jj = warp; jj < 64; jj += 8) {
            const float* r = Grow + (jh * 64 + jj) * LL;
            float s0 = (lane      < nk) ? g1[lane]      + r[lane]      : NEG;
            float s1 = (lane + 32 < nk) ? g1[lane + 32] + r[lane + 32] : NEG;
            float s2 = (lane + 64 < nk) ? g1[lane + 64] + r[lane + 64] : NEG;
            float s3 = (lane + 96 < nk) ? g1[lane + 96] + r[lane + 96] : NEG;
            float m = fmaxf(fmaxf(s0, s1), fmaxf(s2, s3));
            #pragma unroll
            for (int o = 16; o; o >>= 1) m = fmaxf(m, __shfl_xor_sync(0xffffffffu, m, o));
            float e0 = __expf(s0 - m), e1 = __expf(s1 - m);
            float e2 = __expf(s2 - m), e3 = __expf(s3 - m);
            float su = e0 + e1 + e2 + e3;
            #pragma unroll
            for (int o = 16; o; o >>= 1) su += __shfl_xor_sync(0xffffffffu, su, o);
            float inv = 1.0f / su;
            float vals[4] = {e0 * inv, e1 * inv, e2 * inv, e3 * inv};
            #pragma unroll
            for (int c = 0; c < 4; c++) {
                int k = lane + c * 32;
                float x = vals[c];
                __nv_bfloat16 h = __float2bfloat16(x);
                __nv_bfloat16 l = __float2bfloat16(x - __bfloat162float(h));
                sPhi[jj * PSTR + k] = h;
                sPlo[jj * PSTR + k] = l;
            }
        }
    };

    // ---- prologue: async tile0 -> buf0, softmax side 0 under its flight ----
    load_tile_async(0, 0, 0);
    __syncthreads();                 // sG1/sG1q/sW/sBi visible
    softmax_side(G2, sG1);
    CP_WAIT0();
    __syncthreads();

    float ls1[4] = {}, ls2[4] = {};

    // ---- 8 macro-iterations: (side, d-quarter) over 64j x 64d each ----
    #pragma unroll 1
    for (int mi = 0; mi < 8; mi++) {
        int s  = mi >> 2;
        int dq = mi & 3;

        // issue next tile into the ALTERNATE buffer before compute
        if (mi < 7) {
            int nx = mi + 1;
            load_tile_async(nx >> 2, (nx & 3) * 64, nx & 1);
        }

        // ---- MMA: warp tile 32j x 16d, k = 16*nkt, from buf mi&1 ----
        uint32_t bBase = bAddr0 + (uint32_t)((mi & 1) * VBUF);
        float acc[2][2][4] = {};
        uint32_t fA[2][16], fB[2][8];
        load_frags(0, fA[0], fB[0], bBase);
        #pragma unroll 2
        for (int kt = 0; kt < nkt; kt++) {
            int cur = kt & 1;
            if (kt < nkt - 1) load_frags(kt + 1, fA[cur ^ 1], fB[cur ^ 1], bBase);
            const uint32_t* a  = fA[cur];
            const uint32_t* bq = fB[cur];
            // hi*hi
            mma_bf16(acc[0][0], a + 0, bq[0], bq[1]);
            mma_bf16(acc[0][1], a + 0, bq[2], bq[3]);
            mma_bf16(acc[1][0], a + 4, bq[0], bq[1]);
            mma_bf16(acc[1][1], a + 4, bq[2], bq[3]);
            // hi*lo
            mma_bf16(acc[0][0], a + 0, bq[4], bq[5]);
            mma_bf16(acc[0][1], a + 0, bq[6], bq[7]);
            mma_bf16(acc[1][0], a + 4, bq[4], bq[5]);
            mma_bf16(acc[1][1], a + 4, bq[6], bq[7]);
            // lo*hi
            mma_bf16(acc[0][0], a + 8,  bq[0], bq[1]);
            mma_bf16(acc[0][1], a + 8,  bq[2], bq[3]);
            mma_bf16(acc[1][0], a + 12, bq[0], bq[1]);
            mma_bf16(acc[1][1], a + 12, bq[2], bq[3]);
        }

        // ---- store raw output + accumulate LN stats ----
        int colb = s * 256 + dq * 64 + dgroup * 16;
        #pragma unroll
        for (int mt = 0; mt < 2; mt++)
            #pragma unroll
            for (int nt = 0; nt < 2; nt++) {
                const float* a4 = acc[mt][nt];
                int r0 = mbase + mt * 16 + g;           // local row
                int c0 = colb + nt * 8 + tq * 2;
                *(float2*)&outBase[(size_t)r0 * TWO_D + c0] =
                    make_float2(a4[0], a4[1]);
                *(float2*)&outBase[(size_t)(r0 + 8) * TWO_D + c0] =
                    make_float2(a4[2], a4[3]);
                ls1[mt * 2 + 0] += a4[0] + a4[1];
                ls2[mt * 2 + 0] = fmaf(a4[0], a4[0], fmaf(a4[1], a4[1], ls2[mt * 2 + 0]));
                ls1[mt * 2 + 1] += a4[2] + a4[3];
                ls2[mt * 2 + 1] = fmaf(a4[2], a4[2], fmaf(a4[3], a4[3], ls2[mt * 2 + 1]));
            }

        // side-1 softmax: after all side-0 P reads (barrier), while the
        // next tile's cp.async is still in flight.
        if (mi == 3) {
            __syncthreads();
            softmax_side(G2q, sG1q);
        }

        CP_WAIT0();               // next tile landed (no-op cost if done)
        __syncthreads();          // all warps: tile ready / buffers reusable
    }

    // ---- LN stats: shfl-reduce across quad lanes, then smem reduce ----
    #pragma unroll
    for (int ss = 0; ss < 4; ss++) {
        float v1 = ls1[ss], v2 = ls2[ss];
        v1 += __shfl_xor_sync(0xffffffffu, v1, 1);
        v1 += __shfl_xor_sync(0xffffffffu, v1, 2);
        v2 += __shfl_xor_sync(0xffffffffu, v2, 1);
        v2 += __shfl_xor_sync(0xffffffffu, v2, 2);
        if (tq == 0) {
            int row = mbase + (ss >> 1) * 16 + (ss & 1) * 8 + g;   // local
            sST1[row * 4 + dgroup] = v1;
            sST2[row * 4 + dgroup] = v2;
        }
    }
    __syncthreads();
    if (t < 64) {
        float a1 = sST1[t * 4 + 0] + sST1[t * 4 + 1] + sST1[t * 4 + 2] + sST1[t * 4 + 3];
        float a2 = sST2[t * 4 + 0] + sST2[t * 4 + 1] + sST2[t * 4 + 2] + sST2[t * 4 + 3];
        float mu  = a1 * (1.0f / 512.0f);
        float var = a2 * (1.0f / 512.0f) - mu * mu;
        sMu[t] = mu;
        sRs[t] = rsqrtf(var + 1e-5f);
    }
    __syncthreads();

    // ---- Phase C: LayerNorm in place (region is L2-hot) ----
    int jr = t >> 2, part = t & 3;                  // local row, 4 thr/row
    float mu = sMu[jr], rs = sRs[jr];
    float* orow = outBase + (size_t)jr * TWO_D;
    #pragma unroll 4
    for (int itc = 0; itc < 32; itc++) {
        int idx4 = itc * 4 + part;       // 0..127
        int d = idx4 * 4;
        float4 x = *(float4*)&orow[d];
        x.x = (x.x - mu) * rs * sW[d + 0] + sBi[d + 0];
        x.y = (x.y - mu) * rs * sW[d + 1] + sBi[d + 1];
        x.z = (x.z - mu) * rs * sW[d + 2] + sBi[d + 2];
        x.w = (x.w - mu) * rs * sW[d + 3] + sBi[d + 3];
        *(float4*)&orow[d] = x;
    }
}

// ---------------------------------------------------------------------------
extern "C" void kernel_launch(void* const* d_in, const int* in_sizes, int n_in,
                              void* d_out, int out_size)
{
    const float* q    = (const float*)d_in[0];
    const float* v    = (const float*)d_in[1];
    const int*   mask = (const int*)d_in[2];
    const float* nw   = (const float*)d_in[3];
    const float* nb   = (const float*)d_in[4];
    float* out = (float*)d_out;

    gram_kernel<<<dim3(32, BB), 256>>>(q, v, mask);

    cudaFuncSetAttribute(attn_kernel,
                         cudaFuncAttributeMaxDynamicSharedMemorySize, SMEM_BYTES);
    attn_kernel<<<2 * BB * LL, NT, SMEM_BYTES>>>(q, v, mask, nw, nb, out);
}